// round 16
// baseline (speedup 1.0000x reference)
#include <cuda_runtime.h>
#include <cuda_bf16.h>
#include <cstdint>

// ---------------- problem constants ----------------
#define BB   16
#define CC_  128
#define ZD   128
#define NG   8
#define EPSV 1e-5f
#define NW1  (CC_*CC_*9)        // 147456
#define IMG  (CC_*64*64)        // 524288
#define GRPN (16*64*64)         // 65536

// ---------------- scratch (alloc-free) ----------------
__device__ float g_w1[BB*NW1];      // hypernet out, [b][oc][ci*9+pos]
__device__ float g_w2[BB*NW1];
// B fragments, mma.sync b-frag order:
// [b][cc(36)][wn(4)] x 256 uint4 = [s(2)][hl(2)][grp(2)][lane(32)]
__device__ uint4 g_wf1[BB*36*4*256];
__device__ uint4 g_wf2[BB*36*4*256];
__device__ float g_buf1[BB*IMG];    // conv1 raw out
__device__ float g_bufn[BB*IMG];    // conv1 out, GN1+ReLU applied
__device__ float g_buf2[BB*IMG];    // conv2 raw out
__device__ float g_stats1[BB*NG*2];
__device__ float g_stats2[BB*NG*2];
__device__ float g_mi1[BB*NG*2];
__device__ float g_mi2[BB*NG*2];

// ---------------- helpers (sm_80 baseline PTX) ----------------
__device__ __forceinline__ uint32_t smem_u32(const void* p) {
    uint32_t a;
    asm("{ .reg .u64 t; cvta.to.shared.u64 t, %1; cvt.u32.u64 %0, t; }" : "=r"(a) : "l"(p));
    return a;
}
// pack two f32 -> bf16x2 (low half = 'lo' arg)
__device__ __forceinline__ uint32_t cvt2(float hi, float lo) {
    uint32_t r; asm("cvt.rn.bf16x2.f32 %0, %1, %2;" : "=r"(r) : "f"(hi), "f"(lo));
    return r;
}
__device__ __forceinline__ float blo(uint32_t h) { return __uint_as_float(h << 16); }
__device__ __forceinline__ float bhi(uint32_t h) { return __uint_as_float(h & 0xFFFF0000u); }

#define LDSM4(r, addr)                                                        \
    asm volatile("ldmatrix.sync.aligned.m8n8.x4.shared.b16 {%0,%1,%2,%3}, [%4];" \
        : "=r"((r)[0]), "=r"((r)[1]), "=r"((r)[2]), "=r"((r)[3]) : "r"(addr))

#define MMA16816(d, a, b0, b1)                                                \
    asm volatile("mma.sync.aligned.m16n8k16.row.col.f32.bf16.bf16.f32 "       \
        "{%0,%1,%2,%3}, {%4,%5,%6,%7}, {%8,%9}, {%0,%1,%2,%3};"               \
        : "+f"((d)[0]), "+f"((d)[1]), "+f"((d)[2]), "+f"((d)[3])              \
        : "r"((a)[0]), "r"((a)[1]), "r"((a)[2]), "r"((a)[3]), "r"(b0), "r"(b1))

// ---------------- init: zero stats ----------------
__global__ void init_stats_kernel() {
    int i = threadIdx.x;
    g_stats1[i] = 0.f;
    g_stats2[i] = 0.f;
}

// ---------------- hypernet weight generation (float4) ----------------
template <int HEAD>
__global__ __launch_bounds__(256) void gen_w_kernel(const float* __restrict__ z,
                                                    const float* __restrict__ hw,
                                                    const float* __restrict__ hb) {
    __shared__ float zs[BB*ZD];
    int tid = threadIdx.x;
    for (int e = tid; e < BB*ZD; e += 256) zs[e] = z[e];
    __syncthreads();

    int idx4 = (blockIdx.x * 256 + tid) * 4;       // grid 144 -> 147456
    float* out = (HEAD == 0) ? g_w1 : g_w2;

    float4 bias = *(const float4*)&hb[idx4];
    float acc[BB][4];
#pragma unroll
    for (int b = 0; b < BB; b++) {
        acc[b][0] = bias.x; acc[b][1] = bias.y; acc[b][2] = bias.z; acc[b][3] = bias.w;
    }
#pragma unroll 2
    for (int zd = 0; zd < ZD; zd++) {
        float4 v = *(const float4*)&hw[(size_t)zd * NW1 + idx4];
#pragma unroll
        for (int b = 0; b < BB; b++) {
            float zv = zs[b * ZD + zd];
            acc[b][0] = fmaf(zv, v.x, acc[b][0]);
            acc[b][1] = fmaf(zv, v.y, acc[b][1]);
            acc[b][2] = fmaf(zv, v.z, acc[b][2]);
            acc[b][3] = fmaf(zv, v.w, acc[b][3]);
        }
    }
#pragma unroll
    for (int b = 0; b < BB; b++)
        *(float4*)&out[(size_t)b * NW1 + idx4] =
            make_float4(acc[b][0], acc[b][1], acc[b][2], acc[b][3]);
}

// ---------------- permute to mma b-fragment layout + bf16 hi/lo split ------
// Block: (cig, wn, b*2+head). Stages 32 oc x 288 (32ci x 9pos) floats, emits
// per-lane fragments: dst[((b*36+cc)*4+wn)*256 + s*128 + hl*64 + grp*32 + lane].
__global__ __launch_bounds__(256) void permute_frag_kernel() {
    __shared__ float sm[32 * 288];
    const int cig  = blockIdx.x;            // 0..3
    const int wn   = blockIdx.y;            // 0..3
    const int bz   = blockIdx.z;            // 32 = b*2 + head
    const int b    = bz >> 1;
    const int head = bz & 1;
    const float* src = (head ? g_w2 : g_w1)
                     + (size_t)(b * 128 + wn * 32) * 1152 + cig * 288;
    uint4* dst = (head ? g_wf2 : g_wf1);
    const int tid = threadIdx.x;

    for (int e = tid; e < 32 * 288; e += 256)
        sm[e] = src[(size_t)(e / 288) * 1152 + (e % 288)];
    __syncthreads();

#pragma unroll
    for (int it = 0; it < 9; it++) {
        int e = tid + it * 256;             // < 2304 = 9 pos * 256
        int lane = e & 31;
        int grp  = (e >> 5) & 1;
        int hl   = (e >> 6) & 1;
        int s    = (e >> 7) & 1;
        int pos  = e >> 8;
        int cc   = cig * 9 + pos;
        uint32_t pk[4];
#pragma unroll
        for (int j = 0; j < 2; j++) {
            int n  = (grp * 2 + j) * 8 + (lane >> 2);
            int k0 = s * 16 + (lane & 3) * 2;
            const float* row = &sm[n * 288 + pos];
            float v00 = row[k0 * 9],       v01 = row[(k0 + 1) * 9];
            float v10 = row[(k0 + 8) * 9], v11 = row[(k0 + 9) * 9];
            uint32_t h0 = cvt2(v01, v00);
            uint32_t h1 = cvt2(v11, v10);
            if (hl) {
                pk[j * 2]     = cvt2(v01 - bhi(h0), v00 - blo(h0));
                pk[j * 2 + 1] = cvt2(v11 - bhi(h1), v10 - blo(h1));
            } else {
                pk[j * 2]     = h0;
                pk[j * 2 + 1] = h1;
            }
        }
        dst[(size_t)((b * 36 + cc) * 4 + wn) * 256
            + s * 128 + hl * 64 + grp * 32 + lane] =
            make_uint4(pk[0], pk[1], pk[2], pk[3]);
    }
}

// ---------------- mma.sync bf16x3 implicit-GEMM conv ----------------
// CTA: one sample, 256 px (4 rows x 64 cols) x 128 oc. 4 ci-groups x 9 pos.
// A: padded 6x66 halo strip in smem (57KB dynamic), built ONCE per ci-group;
//    all 9 positions read it via shifted ldmatrix row addresses.
//    Rows: [32ci hi | 32ci lo | 16B pad] = 144B.
// B: fragment-direct LDG.128 from gmem (pre-packed), no smem for B.
// 512 thr: warp grid 4(M)x4(N); warp tile 64px x 32oc.
// D = Ah*Bh + Al*Bh + Ah*Bl.
#define SROW 144
#define STRIPR 396                       // 6 * 66
#define CSMEM (STRIPR * SROW)            // 57024 B

template <int PASS>
__global__ __launch_bounds__(512, 1) void conv_mma_kernel(
        const float* __restrict__ xin) {
    extern __shared__ char smS[];        // STRIPR * SROW

    const float* in  = PASS ? g_bufn  : xin;
    const uint4* wf  = PASS ? g_wf2   : g_wf1;
    float*       out = PASS ? g_buf2  : g_buf1;
    float*       st  = PASS ? g_stats2: g_stats1;

    const int tid  = threadIdx.x;
    const int lane = tid & 31;
    const int wid  = tid >> 5;
    const int wm   = wid & 3;            // 4 M-slices of 64 px
    const int wn   = wid >> 2;           // 4 N-slices of 32 oc
    const int b    = blockIdx.y;
    const int y0   = blockIdx.x * 4;

    const float* inb = in + ((size_t)b << 19);
    const uint32_t sS = smem_u32(smS);

    // per-lane ldmatrix row base (strip row for dy=dx=0) per mi
    uint32_t abase[4];
#pragma unroll
    for (int mi = 0; mi < 4; mi++) {
        int px  = wm * 64 + mi * 16 + (lane & 15);
        int ply = px >> 6, plx = px & 63;
        abase[mi] = sS + (uint32_t)((ply + 1) * 66 + (plx + 1)) * SROW
                  + ((lane >> 4) << 4);
    }

    float d[4][4][4];
#pragma unroll
    for (int mi = 0; mi < 4; mi++)
#pragma unroll
        for (int ni = 0; ni < 4; ni++)
#pragma unroll
            for (int k = 0; k < 4; k++) d[mi][ni][k] = 0.f;

    for (int cig = 0; cig < 4; cig++) {
        __syncthreads();                 // strip reads of prev cig done
        // ---- build halo strip: 396 rows x 32 ci, hi/lo split ----
        for (int t = tid; t < 792; t += 512) {
            int row = t >> 1, half = t & 1;
            int sy = row / 66, sx = row - sy * 66;
            int gy = y0 + sy - 1, gx = sx - 1;
            bool ok = ((unsigned)gy < 64u) & ((unsigned)gx < 64u);
            const float* src = inb + ((size_t)(cig * 32 + half * 16) << 12)
                             + (gy << 6) + gx;
            float va[16];
#pragma unroll
            for (int j = 0; j < 16; j++)
                va[j] = ok ? src[(size_t)j << 12] : 0.f;
            uint32_t hp[8], lp[8];
#pragma unroll
            for (int j = 0; j < 8; j++) {
                float a0 = va[2*j], a1 = va[2*j+1];
                uint32_t h = cvt2(a1, a0);
                hp[j] = h;
                lp[j] = cvt2(a1 - bhi(h), a0 - blo(h));
            }
            char* rp = smS + row * SROW + half * 32;
            *(uint4*)(rp)           = make_uint4(hp[0], hp[1], hp[2], hp[3]);
            *(uint4*)(rp + 16)      = make_uint4(hp[4], hp[5], hp[6], hp[7]);
            *(uint4*)(rp + 64)      = make_uint4(lp[0], lp[1], lp[2], lp[3]);
            *(uint4*)(rp + 64 + 16) = make_uint4(lp[4], lp[5], lp[6], lp[7]);
        }
        __syncthreads();

        // ---- 9 kernel positions: pure compute from strip + gmem B frags ----
#pragma unroll
        for (int pos = 0; pos < 9; pos++) {
            const int dy = pos / 3 - 1, dx = pos % 3 - 1;
            const int ioff = (dy * 66 + dx) * SROW;
            const int cc = cig * 9 + pos;
            const uint4* wp = wf + (size_t)((b * 36 + cc) * 4 + wn) * 256 + lane;
#pragma unroll
            for (int s = 0; s < 2; s++) {
                uint4 b0 = wp[s * 128];            // bh ni0,ni1
                uint4 b1 = wp[s * 128 + 32];       // bh ni2,ni3
                uint32_t a_hi[4][4], a_lo[4][4];
#pragma unroll
                for (int mi = 0; mi < 4; mi++)
                    LDSM4(a_hi[mi], abase[mi] + ioff + s * 32);
#pragma unroll
                for (int mi = 0; mi < 4; mi++)
                    LDSM4(a_lo[mi], abase[mi] + ioff + s * 32 + 64);
#pragma unroll
                for (int mi = 0; mi < 4; mi++) {   // Ah*Bh
                    MMA16816(d[mi][0], a_hi[mi], b0.x, b0.y);
                    MMA16816(d[mi][1], a_hi[mi], b0.z, b0.w);
                    MMA16816(d[mi][2], a_hi[mi], b1.x, b1.y);
                    MMA16816(d[mi][3], a_hi[mi], b1.z, b1.w);
                }
#pragma unroll
                for (int mi = 0; mi < 4; mi++) {   // Al*Bh
                    MMA16816(d[mi][0], a_lo[mi], b0.x, b0.y);
                    MMA16816(d[mi][1], a_lo[mi], b0.z, b0.w);
                    MMA16816(d[mi][2], a_lo[mi], b1.x, b1.y);
                    MMA16816(d[mi][3], a_lo[mi], b1.z, b1.w);
                }
                b0 = wp[s * 128 + 64];             // bl ni0,ni1
                b1 = wp[s * 128 + 96];             // bl ni2,ni3
#pragma unroll
                for (int mi = 0; mi < 4; mi++) {   // Ah*Bl
                    MMA16816(d[mi][0], a_hi[mi], b0.x, b0.y);
                    MMA16816(d[mi][1], a_hi[mi], b0.z, b0.w);
                    MMA16816(d[mi][2], a_hi[mi], b1.x, b1.y);
                    MMA16816(d[mi][3], a_hi[mi], b1.z, b1.w);
                }
            }
        }
    }

    // ---- epilogue: store raw + GN partial stats ----
    {
        float* ob = out + ((size_t)b << 19) + (y0 << 6);
        float s0 = 0.f, s1 = 0.f, q0 = 0.f, q1 = 0.f;
#pragma unroll
        for (int mi = 0; mi < 4; mi++) {
            int rb = wm * 64 + mi * 16 + (lane >> 2);
#pragma unroll
            for (int ni = 0; ni < 4; ni++) {
                int col = wn * 32 + ni * 8 + (lane & 3) * 2;
#pragma unroll
                for (int rh = 0; rh < 2; rh++) {
                    int r = rb + rh * 8;
                    float v0 = d[mi][ni][rh * 2];
                    float v1 = d[mi][ni][rh * 2 + 1];
                    ob[((size_t)col << 12) + r]       = v0;
                    ob[((size_t)(col + 1) << 12) + r] = v1;
                    if (ni < 2) { s0 += v0 + v1; q0 += v0*v0 + v1*v1; }
                    else        { s1 += v0 + v1; q1 += v0*v0 + v1*v1; }
                }
            }
        }
#pragma unroll
        for (int off = 16; off; off >>= 1) {
            s0 += __shfl_down_sync(0xffffffffu, s0, off);
            q0 += __shfl_down_sync(0xffffffffu, q0, off);
            s1 += __shfl_down_sync(0xffffffffu, s1, off);
            q1 += __shfl_down_sync(0xffffffffu, q1, off);
        }
        if (lane == 0) {
            int g = wn * 2;
            atomicAdd(&st[(b * NG + g) * 2],         s0);
            atomicAdd(&st[(b * NG + g) * 2 + 1],     q0);
            atomicAdd(&st[(b * NG + g + 1) * 2],     s1);
            atomicAdd(&st[(b * NG + g + 1) * 2 + 1], q1);
        }
    }
}

// ---------------- finalize group stats ----------------
template <int PASS>
__global__ void finalize_kernel() {
    const float* st = (PASS == 0) ? g_stats1 : g_stats2;
    float*       mi = (PASS == 0) ? g_mi1    : g_mi2;
    int i = threadIdx.x;                    // 128 = 16 b * 8 g
    float sum = st[i * 2], sq = st[i * 2 + 1];
    const float invN = 1.f / (float)GRPN;
    float mean = sum * invN;
    float var  = sq * invN - mean * mean;
    mi[i * 2]     = mean;
    mi[i * 2 + 1] = rsqrtf(var + EPSV);
}

// ---------------- normalize conv1 out: GN1 + ReLU (float4) ----------------
__global__ void normalize1_kernel(const float* __restrict__ gamma,
                                  const float* __restrict__ beta) {
    int idx = (blockIdx.x * 256 + threadIdx.x) * 4;
    int c = (idx >> 12) & 127;
    int b = idx >> 19;
    int mg = (b * NG + (c >> 4)) * 2;
    float mean = g_mi1[mg], inv = g_mi1[mg + 1];
    float ga = gamma[c], be = beta[c];
    float4 v = *(const float4*)&g_buf1[idx];
    float4 r;
    r.x = fmaxf(fmaf((v.x - mean) * inv, ga, be), 0.f);
    r.y = fmaxf(fmaf((v.y - mean) * inv, ga, be), 0.f);
    r.z = fmaxf(fmaf((v.z - mean) * inv, ga, be), 0.f);
    r.w = fmaxf(fmaf((v.w - mean) * inv, ga, be), 0.f);
    *(float4*)&g_bufn[idx] = r;
}

// ---------------- epilogue: GN2 + residual + ReLU (float4) ----------------
__global__ void epilogue_kernel(const float* __restrict__ x,
                                const float* __restrict__ gamma,
                                const float* __restrict__ beta,
                                float* __restrict__ out) {
    int idx = (blockIdx.x * 256 + threadIdx.x) * 4;
    int c = (idx >> 12) & 127;
    int b = idx >> 19;
    int mg = (b * NG + (c >> 4)) * 2;
    float mean = g_mi2[mg], inv = g_mi2[mg + 1];
    float ga = gamma[c], be = beta[c];
    float4 v  = *(const float4*)&g_buf2[idx];
    float4 xi = *(const float4*)&x[idx];
    float4 r;
    r.x = fmaxf(fmaf((v.x - mean) * inv, ga, be) + xi.x, 0.f);
    r.y = fmaxf(fmaf((v.y - mean) * inv, ga, be) + xi.y, 0.f);
    r.z = fmaxf(fmaf((v.z - mean) * inv, ga, be) + xi.z, 0.f);
    r.w = fmaxf(fmaf((v.w - mean) * inv, ga, be) + xi.w, 0.f);
    *(float4*)&out[idx] = r;
}

// ---------------- launch ----------------
extern "C" void kernel_launch(void* const* d_in, const int* in_sizes, int n_in,
                              void* d_out, int out_size) {
    const float* x   = (const float*)d_in[0];
    const float* z   = (const float*)d_in[1];
    const float* h1w = (const float*)d_in[2];
    const float* h1b = (const float*)d_in[3];
    const float* h2w = (const float*)d_in[4];
    const float* h2b = (const float*)d_in[5];
    const float* g1  = (const float*)d_in[6];
    const float* b1  = (const float*)d_in[7];
    const float* g2  = (const float*)d_in[8];
    const float* b2  = (const float*)d_in[9];
    float* out = (float*)d_out;

    cudaFuncSetAttribute(conv_mma_kernel<0>,
                         cudaFuncAttributeMaxDynamicSharedMemorySize, CSMEM);
    cudaFuncSetAttribute(conv_mma_kernel<1>,
                         cudaFuncAttributeMaxDynamicSharedMemorySize, CSMEM);

    init_stats_kernel<<<1, 256>>>();
    gen_w_kernel<0><<<NW1 / 1024, 256>>>(z, h1w, h1b);
    gen_w_kernel<1><<<NW1 / 1024, 256>>>(z, h2w, h2b);

    dim3 pgrid(4, 4, 32);                   // cig, wn, b*2+head
    permute_frag_kernel<<<pgrid, 256>>>();

    dim3 cgrid(16, 16);                     // px-tiles (4 rows), batch
    conv_mma_kernel<0><<<cgrid, 512, CSMEM>>>(x);
    finalize_kernel<0><<<1, 128>>>();
    normalize1_kernel<<<(BB * IMG) / 1024, 256>>>(g1, b1);
    conv_mma_kernel<1><<<cgrid, 512, CSMEM>>>(x);
    finalize_kernel<1><<<1, 128>>>();
    epilogue_kernel<<<(BB * IMG) / 1024, 256>>>(x, g2, b2, out);
}